// round 11
// baseline (speedup 1.0000x reference)
#include <cuda_runtime.h>
#include <cstdint>

// PatchTransformer R11: maximize bytes-in-flight per warp. 4px/thread via
// float4 (3x LDG.128 per thread vs R8's 3x LDG.32), 128-thread blocks
// (16x8 -> 64x8 tiles, 2048 blocks) for fine-grained balance, block-uniform
// ballot candidate mask. Exact-fp replication of the reference grid_sample
// chain (rn intrinsics block FMA contraction): reference gates on mask==1.0
// and adv==0.0 equality.

#define S 1024
#define PS 256
#define NP 8

__global__ __launch_bounds__(128, 12)
void patch_transformer_kernel(const float* __restrict__ patches,   // [8,3,256,256]
                              const float* __restrict__ locs,      // [8,2]
                              const float* __restrict__ clean,     // [3,1024,1024]
                              float* __restrict__ out)             // [3,1024,1024]
{
    __shared__ float s_loc[2 * NP];
    __shared__ unsigned s_cmask;

    const int tid = threadIdx.y * 16 + threadIdx.x;
    if (tid < 2 * NP) s_loc[tid] = locs[tid];

    const int bw0 = blockIdx.x * 64;
    const int bh0 = blockIdx.y * 8;

    // Warp 0: block-uniform candidate mask. Conservative: exact sample coord
    // x == w - 512*lx to within <1e-3 px; a pixel can touch patch data only
    // if x in [-1,257). +-2 px margin keeps it strictly conservative.
    if (tid < 32) {
        bool hit = false;
        if (tid < NP) {
            const float px = 512.0f * __ldg(locs + 2 * tid + 0);
            const float py = 512.0f * __ldg(locs + 2 * tid + 1);
            hit = ((float)bw0        <= px + 258.0f) &&
                  ((float)(bw0 + 63) >= px - 2.0f)   &&
                  ((float)bh0        <= py + 258.0f) &&
                  ((float)(bh0 + 7)  >= py - 2.0f);
        }
        const unsigned bal = __ballot_sync(0xFFFFFFFFu, hit);
        if (tid == 0) s_cmask = bal & 0xFFu;
    }
    __syncthreads();

    const int w0 = bw0 + threadIdx.x * 4;
    const int h  = bh0 + threadIdx.y;
    const int pix = h * S + w0;

    // 48 bytes in flight per thread (3x LDG.128).
    float4 a0 = *(const float4*)(clean + pix);
    float4 a1 = *(const float4*)(clean + pix + S * S);
    float4 a2 = *(const float4*)(clean + pix + 2 * S * S);

    unsigned cmask = s_cmask;
    if (cmask) {
        float v[3][4] = {{a0.x, a0.y, a0.z, a0.w},
                         {a1.x, a1.y, a1.z, a1.w},
                         {a2.x, a2.y, a2.z, a2.w}};

        // Normalized grid y coord, exact reference chain (exact fp32 steps).
        const float gy = __fadd_rn(__fmul_rn(__fmul_rn(__fadd_rn((float)h, 0.5f), 2.0f),
                                             (1.0f / 1024.0f)), -1.0f);

        do {
            const int n = __ffs(cmask) - 1;   // ascending = reference paste order
            cmask &= cmask - 1;

            const float lx = s_loc[2 * n + 0];
            const float ly = s_loc[2 * n + 1];

            // y chain shared by the thread's 4 pixels (same h).
            const float gry = __fadd_rn(gy, -ly);
            const float y = __fmul_rn(__fadd_rn(__fmul_rn(__fadd_rn(gry, 1.0f), 1024.0f), -1.0f), 0.5f);
            const float y0f = floorf(y);
            const int iy0 = (int)y0f;
            if ((unsigned)(iy0 + 1) > 256u) continue;

            const float wy1 = __fadd_rn(y, -y0f);
            const float wy0 = __fadd_rn(1.0f, -wy1);
            const bool vy0 = (iy0 >= 0);
            const bool cy1 = (iy0 <= PS - 2);

            const float* P = patches + (size_t)n * 3 * PS * PS;
            const int rowoff = iy0 * PS;

            #pragma unroll
            for (int k = 0; k < 4; ++k) {
                // Normalized grid x coord for pixel w0+k (exact fp32 steps).
                const float gx = __fadd_rn(__fmul_rn(__fmul_rn(__fadd_rn((float)(w0 + k), 0.5f), 2.0f),
                                                     (1.0f / 1024.0f)), -1.0f);
                const float grx = __fadd_rn(gx, -lx);
                const float x = __fmul_rn(__fadd_rn(__fmul_rn(__fadd_rn(grx, 1.0f), 1024.0f), -1.0f), 0.5f);
                const float x0f = floorf(x);
                const int ix0 = (int)x0f;
                if ((unsigned)(ix0 + 1) > 256u) continue;

                const float wx1 = __fadd_rn(x, -x0f);
                const float wx0 = __fadd_rn(1.0f, -wx1);

                const float w00 = __fmul_rn(wy0, wx0);
                const float w01 = __fmul_rn(wy0, wx1);
                const float w10 = __fmul_rn(wy1, wx0);
                const float w11 = __fmul_rn(wy1, wx1);

                const bool vx0 = (ix0 >= 0);
                // mask_w = left-associated sum of valid*weight, exactly as
                // reference (+1 taps always frame-valid inside footprint).
                const float msum = __fadd_rn(__fadd_rn(__fadd_rn(
                                       (vy0 && vx0) ? w00 : 0.0f,
                                       vy0 ? w01 : 0.0f),
                                       vx0 ? w10 : 0.0f),
                                       w11);
                if (msum != 1.0f) continue;

                const bool cx1 = (ix0 <= PS - 2);
                const bool t00v = vy0 && vx0;
                const bool t01v = vy0 && cx1;
                const bool t10v = cy1 && vx0;
                const bool t11v = cy1 && cx1;
                if (!(t00v | t01v | t10v | t11v)) continue;

                const int o00 = rowoff + ix0;
                #pragma unroll
                for (int c = 0; c < 3; ++c) {
                    const float* B = P + c * PS * PS;
                    const float t00 = t00v ? __fmul_rn(__ldg(B + o00),          w00) : 0.0f;
                    const float t01 = t01v ? __fmul_rn(__ldg(B + o00 + 1),      w01) : 0.0f;
                    const float t10 = t10v ? __fmul_rn(__ldg(B + o00 + PS),     w10) : 0.0f;
                    const float t11 = t11v ? __fmul_rn(__ldg(B + o00 + PS + 1), w11) : 0.0f;
                    const float p = __fadd_rn(__fadd_rn(__fadd_rn(t00, t01), t10), t11);
                    if (p != 0.0f) v[c][k] = p;
                }
            }
        } while (cmask);

        a0 = make_float4(v[0][0], v[0][1], v[0][2], v[0][3]);
        a1 = make_float4(v[1][0], v[1][1], v[1][2], v[1][3]);
        a2 = make_float4(v[2][0], v[2][1], v[2][2], v[2][3]);
    }

    *(float4*)(out + pix)             = a0;
    *(float4*)(out + pix + S * S)     = a1;
    *(float4*)(out + pix + 2 * S * S) = a2;
}

extern "C" void kernel_launch(void* const* d_in, const int* in_sizes, int n_in,
                              void* d_out, int out_size) {
    const float* patches = (const float*)d_in[0];   // (8,3,256,256)
    const float* locs    = (const float*)d_in[1];   // (8,2)
    const float* clean   = (const float*)d_in[2];   // (3,1024,1024)
    float* out = (float*)d_out;                     // (1,3,1024,1024)

    dim3 block(16, 8);                  // 128 threads, 4 px/thread (float4)
    dim3 grid(S / 64, S / 8);           // 16 x 128 = 2048 blocks (64x8 tiles)
    patch_transformer_kernel<<<grid, block>>>(patches, locs, clean, out);
}

// round 12
// speedup vs baseline: 1.4006x; 1.4006x over previous
#include <cuda_runtime.h>
#include <cstdint>

// PatchTransformer R12: 4096 fine tiles (32x8, proven best balance) with
// 128-thread blocks, 2px/thread float2 (half the mem instructions), and a
// warp-level candidate mask (ballot + shfl, no shared memory, no syncthreads).
// Exact-fp replication of the reference grid_sample chain (rn intrinsics
// block FMA contraction): reference gates on mask==1.0 and adv==0.0 equality.

#define S 1024
#define PS 256
#define NP 8

__global__ __launch_bounds__(128, 16)
void patch_transformer_kernel(const float* __restrict__ patches,   // [8,3,256,256]
                              const float* __restrict__ locs,      // [8,2]
                              const float* __restrict__ clean,     // [3,1024,1024]
                              float* __restrict__ out)             // [3,1024,1024]
{
    const int tid  = threadIdx.y * 16 + threadIdx.x;   // 0..127
    const int lane = tid & 31;

    const int bw0 = blockIdx.x * 32;
    const int bh0 = blockIdx.y * 8;

    const int w0 = bw0 + threadIdx.x * 2;
    const int h  = bh0 + threadIdx.y;
    const int pix = h * S + w0;

    // Issue clean loads first; mask computation overlaps their latency.
    float2 a0 = *(const float2*)(clean + pix);
    float2 a1 = *(const float2*)(clean + pix + S * S);
    float2 a2 = *(const float2*)(clean + pix + 2 * S * S);

    // Per-lane patch location preload (lanes 0..7 own one patch each).
    float plx = 0.0f, ply = 0.0f;
    if (lane < NP) {
        plx = __ldg(locs + 2 * lane + 0);
        ply = __ldg(locs + 2 * lane + 1);
    }

    // Warp-level candidate mask over this warp's 32x2 strip.
    // Conservative: exact sample coord x == w - 512*lx to within <1e-3 px;
    // a pixel can touch patch data only if x in [-1,257). +-2 px margin.
    const int hy0 = bh0 + 2 * (tid >> 5);   // warp covers rows hy0, hy0+1
    bool hit = false;
    if (lane < NP) {
        const float px = 512.0f * plx;
        const float py = 512.0f * ply;
        hit = ((float)bw0        <= px + 258.0f) &&
              ((float)(bw0 + 31) >= px - 2.0f)   &&
              ((float)hy0        <= py + 258.0f) &&
              ((float)(hy0 + 1)  >= py - 2.0f);
    }
    unsigned cmask = __ballot_sync(0xFFFFFFFFu, hit) & 0xFFu;   // warp-uniform

    if (cmask) {
        float v[3][2] = {{a0.x, a0.y}, {a1.x, a1.y}, {a2.x, a2.y}};

        // Normalized grid coords, exact reference chain (all steps exact fp32).
        const float gy = __fadd_rn(__fmul_rn(__fmul_rn(__fadd_rn((float)h, 0.5f), 2.0f),
                                             (1.0f / 1024.0f)), -1.0f);
        float gxk[2];
        #pragma unroll
        for (int k = 0; k < 2; ++k)
            gxk[k] = __fadd_rn(__fmul_rn(__fmul_rn(__fadd_rn((float)(w0 + k), 0.5f), 2.0f),
                                         (1.0f / 1024.0f)), -1.0f);

        do {
            const int n = __ffs(cmask) - 1;   // ascending = reference paste order
            cmask &= cmask - 1;

            const float lx = __shfl_sync(0xFFFFFFFFu, plx, n);
            const float ly = __shfl_sync(0xFFFFFFFFu, ply, n);

            // y chain shared by the thread's 2 pixels (same h).
            const float gry = __fadd_rn(gy, -ly);
            const float y = __fmul_rn(__fadd_rn(__fmul_rn(__fadd_rn(gry, 1.0f), 1024.0f), -1.0f), 0.5f);
            const float y0f = floorf(y);
            const int iy0 = (int)y0f;
            if ((unsigned)(iy0 + 1) > 256u) continue;

            const float wy1 = __fadd_rn(y, -y0f);
            const float wy0 = __fadd_rn(1.0f, -wy1);
            const bool vy0 = (iy0 >= 0);
            const bool cy1 = (iy0 <= PS - 2);

            const float* P = patches + (size_t)n * 3 * PS * PS;
            const int rowoff = iy0 * PS;

            #pragma unroll
            for (int k = 0; k < 2; ++k) {
                const float grx = __fadd_rn(gxk[k], -lx);
                const float x = __fmul_rn(__fadd_rn(__fmul_rn(__fadd_rn(grx, 1.0f), 1024.0f), -1.0f), 0.5f);
                const float x0f = floorf(x);
                const int ix0 = (int)x0f;
                if ((unsigned)(ix0 + 1) > 256u) continue;

                const float wx1 = __fadd_rn(x, -x0f);
                const float wx0 = __fadd_rn(1.0f, -wx1);

                const float w00 = __fmul_rn(wy0, wx0);
                const float w01 = __fmul_rn(wy0, wx1);
                const float w10 = __fmul_rn(wy1, wx0);
                const float w11 = __fmul_rn(wy1, wx1);

                const bool vx0 = (ix0 >= 0);
                // mask_w = left-associated sum of valid*weight, exactly as
                // reference (+1 taps always frame-valid inside footprint).
                const float msum = __fadd_rn(__fadd_rn(__fadd_rn(
                                       (vy0 && vx0) ? w00 : 0.0f,
                                       vy0 ? w01 : 0.0f),
                                       vx0 ? w10 : 0.0f),
                                       w11);
                if (msum != 1.0f) continue;

                const bool cx1 = (ix0 <= PS - 2);
                const bool t00v = vy0 && vx0;
                const bool t01v = vy0 && cx1;
                const bool t10v = cy1 && vx0;
                const bool t11v = cy1 && cx1;
                if (!(t00v | t01v | t10v | t11v)) continue;

                const int o00 = rowoff + ix0;
                #pragma unroll
                for (int c = 0; c < 3; ++c) {
                    const float* B = P + c * PS * PS;
                    const float t00 = t00v ? __fmul_rn(__ldg(B + o00),          w00) : 0.0f;
                    const float t01 = t01v ? __fmul_rn(__ldg(B + o00 + 1),      w01) : 0.0f;
                    const float t10 = t10v ? __fmul_rn(__ldg(B + o00 + PS),     w10) : 0.0f;
                    const float t11 = t11v ? __fmul_rn(__ldg(B + o00 + PS + 1), w11) : 0.0f;
                    const float p = __fadd_rn(__fadd_rn(__fadd_rn(t00, t01), t10), t11);
                    if (p != 0.0f) v[c][k] = p;
                }
            }
        } while (cmask);

        a0 = make_float2(v[0][0], v[0][1]);
        a1 = make_float2(v[1][0], v[1][1]);
        a2 = make_float2(v[2][0], v[2][1]);
    }

    *(float2*)(out + pix)             = a0;
    *(float2*)(out + pix + S * S)     = a1;
    *(float2*)(out + pix + 2 * S * S) = a2;
}

extern "C" void kernel_launch(void* const* d_in, const int* in_sizes, int n_in,
                              void* d_out, int out_size) {
    const float* patches = (const float*)d_in[0];   // (8,3,256,256)
    const float* locs    = (const float*)d_in[1];   // (8,2)
    const float* clean   = (const float*)d_in[2];   // (3,1024,1024)
    float* out = (float*)d_out;                     // (1,3,1024,1024)

    dim3 block(16, 8);                  // 128 threads, 2 px/thread (float2)
    dim3 grid(S / 32, S / 8);           // 32 x 128 = 4096 blocks (32x8 tiles)
    patch_transformer_kernel<<<grid, block>>>(patches, locs, clean, out);
}